// round 4
// baseline (speedup 1.0000x reference)
#include <cuda_runtime.h>

// out[b,o] = sum_i w_out[o,i] * sin(x[b,i]*w_sin[o,i] + b_sin[o,i]) + b_out[o]
// B=2048, I=256, O=512
// x:      [B, I]     float32
// weight: [O, I, 2]  float32 (interleaved w_out, w_sin)
// bias:   [O, I+1]   float32 (row stride 257; [:,256] = b_out)

#define B_DIM 2048
#define I_DIM 256
#define O_DIM 512

#define B_TILE 128
#define O_TILE 16
#define KC     32       // smem k-chunk
#define LDW    36       // smem row stride in floats (== 4 mod 32 -> conflict-free)

// sin via degree-13 odd Taylor — runs on the FMA pipe, parallel to MUFU.
// abs err < 3e-5 for |a| <= ~3.2; arguments here are bounded ~2.5.
__device__ __forceinline__ float sin_poly(float a)
{
    const float c1 = -1.6666667e-1f;
    const float c2 =  8.3333333e-3f;
    const float c3 = -1.9841270e-4f;
    const float c4 =  2.7557319e-6f;
    const float c5 = -2.5052108e-8f;
    const float c6 =  1.6059044e-10f;
    float y = a * a;
    float p = fmaf(c6, y, c5);
    p = fmaf(p, y, c4);
    p = fmaf(p, y, c3);
    p = fmaf(p, y, c2);
    p = fmaf(p, y, c1);
    p = fmaf(p, y, 1.0f);
    return a * p;
}

__global__ __launch_bounds__(256)
void trigo_main_kernel(const float* __restrict__ x,
                       const float* __restrict__ weight,
                       const float* __restrict__ bias,
                       float* __restrict__ out)
{
    __shared__ float xs [B_TILE][LDW];
    __shared__ float wo [O_TILE][LDW];
    __shared__ float wsn[O_TILE][LDW];
    __shared__ float bsn[O_TILE][LDW];

    const int tid   = threadIdx.x;          // 0..255
    const int oBase = blockIdx.x * O_TILE;
    const int bBase = blockIdx.y * B_TILE;

    const int ox = tid & 7;    // o = oBase + ox + 8j,  j=0..1
    const int by = tid >> 3;   // b = bBase + by + 32i, i=0..3

    float acc[4][2];
#pragma unroll
    for (int i = 0; i < 4; i++)
#pragma unroll
        for (int j = 0; j < 2; j++) acc[i][j] = 0.f;

#pragma unroll 1
    for (int kg = 0; kg < I_DIM; kg += KC) {
        // --- stage x: 128 rows x 32 k, float4 (4 per thread) ---
        {
            const int c  = tid & 7;    // float4 col (8 per row)
            const int r0 = tid >> 3;   // 0..31
#pragma unroll
            for (int p = 0; p < 4; p++) {
                const int r = r0 + 32 * p;
                float4 v = *reinterpret_cast<const float4*>(
                    &x[(size_t)(bBase + r) * I_DIM + kg + c * 4]);
                *reinterpret_cast<float4*>(&xs[r][c * 4]) = v;
            }
        }
        // --- stage weight (deinterleave): 16 rows x 32 i = 256 float4 (1/thread) ---
        {
            const int r = tid >> 4;    // 0..15
            const int c = tid & 15;    // float4 chunk = 2 i's
            float4 v = *reinterpret_cast<const float4*>(
                &weight[(size_t)(oBase + r) * (2 * I_DIM) + 2 * kg + c * 4]);
            wo [r][2 * c    ] = v.x;  wsn[r][2 * c    ] = v.y;
            wo [r][2 * c + 1] = v.z;  wsn[r][2 * c + 1] = v.w;
        }
        // --- stage b_sin: 16 rows x 32 cols, scalar (odd row stride 257) ---
        {
#pragma unroll
            for (int p = 0; p < 2; p++) {
                const int idx = tid + p * 256;   // 0..511
                const int r  = idx >> 5;
                const int cc = idx & 31;
                bsn[r][cc] = bias[(size_t)(oBase + r) * (I_DIM + 1) + kg + cc];
            }
        }
        __syncthreads();

#pragma unroll 1
        for (int k4 = 0; k4 < KC; k4 += 4) {
            float4 wov[2], wsv[2], bsv[2];
#pragma unroll
            for (int j = 0; j < 2; j++) {
                const int r = ox + 8 * j;
                wov[j] = *reinterpret_cast<const float4*>(&wo [r][k4]);
                wsv[j] = *reinterpret_cast<const float4*>(&wsn[r][k4]);
                bsv[j] = *reinterpret_cast<const float4*>(&bsn[r][k4]);
            }
#pragma unroll
            for (int i = 0; i < 4; i++) {
                float4 xv = *reinterpret_cast<const float4*>(&xs[by + 32 * i][k4]);
#pragma unroll
                for (int j = 0; j < 2; j++) {
                    // 1/8 of tile elements on FMA-pipe poly sin, 7/8 on MUFU.
                    const bool poly = (i * 2 + j) == 0;
                    float a0 = fmaf(xv.x, wsv[j].x, bsv[j].x);
                    float a1 = fmaf(xv.y, wsv[j].y, bsv[j].y);
                    float a2 = fmaf(xv.z, wsv[j].z, bsv[j].z);
                    float a3 = fmaf(xv.w, wsv[j].w, bsv[j].w);
                    float s0 = poly ? sin_poly(a0) : __sinf(a0);
                    float s1 = poly ? sin_poly(a1) : __sinf(a1);
                    float s2 = poly ? sin_poly(a2) : __sinf(a2);
                    float s3 = poly ? sin_poly(a3) : __sinf(a3);
                    acc[i][j] = fmaf(wov[j].x, s0, acc[i][j]);
                    acc[i][j] = fmaf(wov[j].y, s1, acc[i][j]);
                    acc[i][j] = fmaf(wov[j].z, s2, acc[i][j]);
                    acc[i][j] = fmaf(wov[j].w, s3, acc[i][j]);
                }
            }
        }
        __syncthreads();
    }

    // --- epilogue: add b_out, write directly to out ---
    float bout[2];
#pragma unroll
    for (int j = 0; j < 2; j++)
        bout[j] = bias[(size_t)(oBase + ox + 8 * j) * (I_DIM + 1) + I_DIM];

#pragma unroll
    for (int i = 0; i < 4; i++) {
        const int b = bBase + by + 32 * i;
#pragma unroll
        for (int j = 0; j < 2; j++) {
            out[(size_t)b * O_DIM + oBase + ox + 8 * j] = acc[i][j] + bout[j];
        }
    }
}

extern "C" void kernel_launch(void* const* d_in, const int* in_sizes, int n_in,
                              void* d_out, int out_size)
{
    const float* x      = (const float*)d_in[0];
    const float* weight = (const float*)d_in[1];
    const float* bias   = (const float*)d_in[2];
    float* out          = (float*)d_out;

    dim3 grid(O_DIM / O_TILE, B_DIM / B_TILE);   // (32,16) = 512 blocks
    trigo_main_kernel<<<grid, 256>>>(x, weight, bias, out);
}